// round 15
// baseline (speedup 1.0000x reference)
#include <cuda_runtime.h>
#include <cstdint>

// ---------------------------------------------------------------------------
// SNN forward — fp32 bit-exact-chain, v7 "packed + contraction-proof".
//   Per-output fp32 FMA chain over ascending k (identical to passing R9-R13),
//   with ALL LIF/bias/reset arithmetic forced to fixed instructions:
//     cur = __fadd_rn(acc, bias); m = __fmaf_rn(0.9f, m, cur);
//     s = (m > 1) ? 1 : 0;        m' = __fsub_rn(m, s);
//   so codegen context cannot change rounding (R14 failure hypothesis).
//   Scheduling: ALL work (L0 slices, L1 tiles, sparse L2, lif0 chunks) on
//   per-launch dynamic ticket queues; L0 slice t+5 computed in launch t.
// Output: [0, 25*256*1024) layer-2 spike record; then (256*1024) final mem2.
// ---------------------------------------------------------------------------

constexpr int T_STEPS = 25;
constexpr int BATCH   = 256;
constexpr int F0 = 1024, F1 = 2048, F2 = 2048, F3 = 1024;
constexpr int M0 = T_STEPS * BATCH;              // 6400

__device__ float g_wt0[F0 * F1];                 // W0^T [k][n]
__device__ float g_wt1[F1 * F2];                 // W1^T [k][n]
__device__ float g_wt2[F2 * F3];                 // W2^T [k][n]
__device__ float g_xT[F0 * M0];                  // x^T  [k][t*B+b]
__device__ float g_cur0T[F1 * M0];               // layer-0 currents [n][t*B+b]
__device__ float g_m0T[F1 * BATCH];              // layer-0 membranes [n][b]
__device__ float g_m1T[F2 * BATCH];              // layer-1 membranes [n][b]
__device__ float g_m2RM[BATCH * F3];             // layer-2 membranes row-major
__device__ float g_s0T[2][F1 * BATCH];           // layer-0 spikes k-major, dbl-buf
__device__ float g_s1RM[2][BATCH * F2];          // layer-1 spikes row-major, dbl-buf
__device__ unsigned int g_tick[32];              // per-launch ticket counters

// ----- fixed-rounding LIF ops (compilation-invariant) --------------------------
__device__ __forceinline__ void lif_update(float mold, float cur,
                                           float& mnew, float& s) {
    float m = __fmaf_rn(0.9f, mold, cur);
    s = (m > 1.0f) ? 1.0f : 0.0f;
    mnew = __fsub_rn(m, s);
}

// ----- packed f32x2 helpers ---------------------------------------------------
__device__ __forceinline__ unsigned long long pk2(float x, float y) {
    unsigned long long r;
    asm("mov.b64 %0, {%1, %2};" : "=l"(r) : "f"(x), "f"(y));
    return r;
}
__device__ __forceinline__ void upk2(float& x, float& y, unsigned long long v) {
    asm("mov.b64 {%0, %1}, %2;" : "=f"(x), "=f"(y) : "l"(v));
}
#define FMA2(acc, a, b) \
    asm("fma.rn.f32x2 %0, %1, %2, %0;" : "+l"(acc) : "l"(a), "l"(b))
#define ADD2(acc, v) \
    asm("add.rn.f32x2 %0, %0, %1;" : "+l"(acc) : "l"(v))

#define CP_ASYNC16(dst, src) \
    asm volatile("cp.async.cg.shared.global [%0], [%1], 16;\n" :: "r"(dst), "l"(src))
#define CP_COMMIT() asm volatile("cp.async.commit_group;\n")
#define CP_WAIT1()  asm volatile("cp.async.wait_group 1;\n")
#define CP_WAIT0()  asm volatile("cp.async.wait_group 0;\n")

__device__ __forceinline__ uint32_t cvta_s(const void* p) {
    return (uint32_t)__cvta_generic_to_shared(p);
}

// ----- prep kernels -------------------------------------------------------------
__global__ void zero_mems_kernel() {
    int idx = blockIdx.x * blockDim.x + threadIdx.x;
    int stride = gridDim.x * blockDim.x;
    for (int i = idx; i < BATCH * F2; i += stride) g_m1T[i] = 0.0f;
    for (int i = idx; i < BATCH * F3; i += stride) g_m2RM[i] = 0.0f;
    if (idx < 32) g_tick[idx] = 0u;
}

__global__ void transpose_kernel(const float* __restrict__ src,
                                 float* __restrict__ dst, int R, int C) {
    __shared__ float tile[32][33];
    int c0 = blockIdx.x * 32, r0 = blockIdx.y * 32;
    int tx = threadIdx.x, ty = threadIdx.y;          // 32 x 8
    #pragma unroll
    for (int j = 0; j < 32; j += 8)
        tile[ty + j][tx] = src[(size_t)(r0 + ty + j) * C + c0 + tx];
    __syncthreads();
    #pragma unroll
    for (int j = 0; j < 32; j += 8)
        dst[(size_t)(c0 + ty + j) * R + r0 + tx] = tile[tx][ty + j];
}

__global__ void copy_final_mem_kernel(float* __restrict__ dst) {
    int i = blockIdx.x * blockDim.x + threadIdx.x;
    if (i < BATCH * F3) dst[i] = g_m2RM[i];
}

// ---------------------------------------------------------------------------
// Unified per-warp 32x32 GEMM tile (K = ktot, BK=16 double-buffered cp.async).
// MODE 0: cur = fadd(acc, bias) -> outT[col][om_off + row]     (layer 0)
// MODE 1: LIF -> m1T (feature-major) + s1 row-major            (layer 1)
// ---------------------------------------------------------------------------
template <int MODE>
__device__ __forceinline__ void warp_gemm_t(
    float* wsm, uint32_t wsm_u,
    const float* __restrict__ A, int astride, int am_off,
    const float* __restrict__ W, int nstride, int ktot,
    const float* __restrict__ bias,
    float* __restrict__ outT, int ostride, int om_off,
    float* __restrict__ s1rm,
    int bm, int bn, int lane)
{
    const int KT = ktot >> 4;
    unsigned long long acc2[8][2];
    #pragma unroll
    for (int i = 0; i < 8; i++) { acc2[i][0] = 0ULL; acc2[i][1] = 0ULL; }

    const int ty = lane >> 3, tx = lane & 7;
    const int am_base = am_off + bm;

    auto issue = [&](int st, int k0) {
        #pragma unroll
        for (int j = 0; j < 4; j++) {
            int c = lane + 32 * j;
            int kr = c >> 3, of = c & 7;
            CP_ASYNC16(wsm_u + (uint32_t)(st * 512 + kr * 32 + of * 4) * 4u,
                       A + (size_t)(k0 + kr) * astride + am_base + of * 4);
        }
        #pragma unroll
        for (int j = 0; j < 4; j++) {
            int c = lane + 32 * j;
            int kr = c >> 3, of = c & 7;
            CP_ASYNC16(wsm_u + (uint32_t)(1024 + st * 512 + kr * 32 + of * 4) * 4u,
                       W + (size_t)(k0 + kr) * nstride + bn + of * 4);
        }
        CP_COMMIT();
    };

    issue(0, 0);
    for (int kt = 0; kt < KT; ++kt) {
        if (kt + 1 < KT) { issue((kt + 1) & 1, (kt + 1) * 16); CP_WAIT1(); }
        else             { CP_WAIT0(); }
        __syncwarp();
        const float* sA = wsm + (kt & 1) * 512;
        const float* sB = wsm + 1024 + (kt & 1) * 512;
        #pragma unroll
        for (int k = 0; k < 16; ++k) {
            float4 a0 = *reinterpret_cast<const float4*>(sA + k * 32 + ty * 8);
            float4 a1 = *reinterpret_cast<const float4*>(sA + k * 32 + ty * 8 + 4);
            float4 bv = *reinterpret_cast<const float4*>(sB + k * 32 + tx * 4);
            unsigned long long bp0 = pk2(bv.x, bv.y), bp1 = pk2(bv.z, bv.w);
            const float a8[8] = {a0.x, a0.y, a0.z, a0.w, a1.x, a1.y, a1.z, a1.w};
            #pragma unroll
            for (int l = 0; l < 8; l++) {
                unsigned long long ad = pk2(a8[l], a8[l]);
                FMA2(acc2[l][0], ad, bp0);
                FMA2(acc2[l][1], ad, bp1);
            }
        }
        __syncwarp();
    }

    const int row0 = bm + ty * 8;
    if (MODE == 0) {
        #pragma unroll
        for (int p = 0; p < 2; p++) {
            #pragma unroll
            for (int q = 0; q < 2; q++) {
                const int col = bn + tx * 4 + p * 2 + q;
                const float bcol = __ldg(&bias[col]);
                float v[8];
                #pragma unroll
                for (int i = 0; i < 8; i++) {
                    float c0, c1;
                    upk2(c0, c1, acc2[i][p]);
                    v[i] = __fadd_rn(q ? c1 : c0, bcol);
                }
                float* cp = outT + (size_t)col * ostride + om_off + row0;
                *reinterpret_cast<float4*>(cp)     = make_float4(v[0], v[1], v[2], v[3]);
                *reinterpret_cast<float4*>(cp + 4) = make_float4(v[4], v[5], v[6], v[7]);
            }
        }
    } else {
        float sreg[8][4];
        #pragma unroll
        for (int p = 0; p < 2; p++) {
            #pragma unroll
            for (int q = 0; q < 2; q++) {
                const int col = bn + tx * 4 + p * 2 + q;
                const float bcol = __ldg(&bias[col]);
                float v[8];
                #pragma unroll
                for (int i = 0; i < 8; i++) {
                    float c0, c1;
                    upk2(c0, c1, acc2[i][p]);
                    v[i] = __fadd_rn(q ? c1 : c0, bcol);
                }
                float* mp = outT + (size_t)col * ostride + row0;
                float4 mlo = *reinterpret_cast<float4*>(mp);
                float4 mhi = *reinterpret_cast<float4*>(mp + 4);
                float mm[8] = {mlo.x, mlo.y, mlo.z, mlo.w, mhi.x, mhi.y, mhi.z, mhi.w};
                float ss[8];
                #pragma unroll
                for (int i = 0; i < 8; i++)
                    lif_update(mm[i], v[i], mm[i], ss[i]);
                *reinterpret_cast<float4*>(mp)     = make_float4(mm[0], mm[1], mm[2], mm[3]);
                *reinterpret_cast<float4*>(mp + 4) = make_float4(mm[4], mm[5], mm[6], mm[7]);
                #pragma unroll
                for (int i = 0; i < 8; i++) sreg[i][p * 2 + q] = ss[i];
            }
        }
        #pragma unroll
        for (int i = 0; i < 8; i++) {
            const int row = row0 + i;
            *reinterpret_cast<float4*>(s1rm + (size_t)row * nstride + bn + tx * 4) =
                make_float4(sreg[i][0], sreg[i][1], sreg[i][2], sreg[i][3]);
        }
    }
}

// ---------------------------------------------------------------------------
// SPARSE layer-2 task (spikes exactly 0/1: skip-zero ADD2 over ascending k
// is bit-identical to the dense FMA chain). LIF via fixed-rounding ops.
// ---------------------------------------------------------------------------
__device__ __forceinline__ void sparse_l2(
    const float* __restrict__ s1b,
    const float* __restrict__ W2T,
    const float* __restrict__ bias,
    float* __restrict__ m2b,
    float* __restrict__ outb,
    int n0, int lane)
{
    unsigned long long acc[4][2];
    #pragma unroll
    for (int c = 0; c < 4; c++) { acc[c][0] = 0ULL; acc[c][1] = 0ULL; }

    for (int base = 0; base < F2; base += 128) {
        const float4 sv = *reinterpret_cast<const float4*>(s1b + base + lane * 4);
        unsigned bl0 = __ballot_sync(0xffffffffu, sv.x != 0.0f);
        unsigned bl1 = __ballot_sync(0xffffffffu, sv.y != 0.0f);
        unsigned bl2 = __ballot_sync(0xffffffffu, sv.z != 0.0f);
        unsigned bl3 = __ballot_sync(0xffffffffu, sv.w != 0.0f);
        unsigned any = bl0 | bl1 | bl2 | bl3;
        while (any) {
            const int L = __ffs(any) - 1;
            any &= any - 1;
            const int kb = base + L * 4;
            #pragma unroll
            for (int j = 0; j < 4; j++) {
                const unsigned blj = (j == 0) ? bl0 : (j == 1) ? bl1 : (j == 2) ? bl2 : bl3;
                if ((blj >> L) & 1u) {
                    const float* wr = W2T + (size_t)(kb + j) * F3 + n0;
                    #pragma unroll
                    for (int c = 0; c < 4; c++) {
                        float4 w = *reinterpret_cast<const float4*>(wr + c * 128 + lane * 4);
                        ADD2(acc[c][0], pk2(w.x, w.y));
                        ADD2(acc[c][1], pk2(w.z, w.w));
                    }
                }
            }
        }
    }

    #pragma unroll
    for (int c = 0; c < 4; c++) {
        const int n = n0 + c * 128 + lane * 4;
        float a0, a1, a2, a3;
        upk2(a0, a1, acc[c][0]);
        upk2(a2, a3, acc[c][1]);
        float4 bv = *reinterpret_cast<const float4*>(bias + n);
        float4 mv = *reinterpret_cast<const float4*>(m2b + n);
        float m0, m1, m2, m3, s0, s1, s2, s3;
        lif_update(mv.x, __fadd_rn(a0, bv.x), m0, s0);
        lif_update(mv.y, __fadd_rn(a1, bv.y), m1, s1);
        lif_update(mv.z, __fadd_rn(a2, bv.z), m2, s2);
        lif_update(mv.w, __fadd_rn(a3, bv.w), m3, s3);
        *reinterpret_cast<float4*>(m2b + n)  = make_float4(m0, m1, m2, m3);
        *reinterpret_cast<float4*>(outb + n) = make_float4(s0, s1, s2, s3);
    }
}

// ---------------------------------------------------------------------------
// Step kernel, dynamic ticket queue:
//   [0, nL1)            : dense layer-1 tiles (512)
//   [nL1, +nL0)         : dense layer-0 tiles (512 per slice)
//   [.., +nSP)          : sparse layer-2 tasks (512)
//   [.., +nLIF)         : lif0 chunks (32); lif_t==0 starts from m=0
// ---------------------------------------------------------------------------
__global__ __launch_bounds__(128)
void step_kernel(int li,
                 int nL1, int l1_par,
                 int nL0, int l0_first,
                 int nSP, int sp_par,
                 int nLIF, int lif_t,
                 const float* __restrict__ b0,
                 const float* __restrict__ b1,
                 const float* __restrict__ b2,
                 float* __restrict__ out_t)
{
    __shared__ float sm[4 * 2048];
    const int warp = threadIdx.x >> 5, lane = threadIdx.x & 31;
    float* wsm = sm + warp * 2048;
    const uint32_t wsm_u = cvta_s(wsm);

    const int total = nL1 + nL0 + nSP + nLIF;
    const float* l1A = g_s0T[l1_par];
    float* l1spk = g_s1RM[l1_par];
    const float* spS = g_s1RM[sp_par];

    for (;;) {
        unsigned int tk;
        if (lane == 0) tk = atomicAdd(&g_tick[li], 1u);
        tk = __shfl_sync(0xffffffffu, tk, 0);
        if (tk >= (unsigned)total) break;

        if ((int)tk < nL1) {
            const int bm = (tk >> 6) * 32, bn = (int)(tk & 63) * 32;
            warp_gemm_t<1>(wsm, wsm_u, l1A, BATCH, 0, g_wt1, F2, F1,
                           b1, g_m1T, BATCH, 0, l1spk, bm, bn, lane);
        } else if ((int)tk < nL1 + nL0) {
            const int j = tk - nL1;
            const int slice = l0_first + (j >> 9);
            const int tile = j & 511;
            const int bm = (tile >> 6) * 32, bn = (tile & 63) * 32;
            const int moff = slice * BATCH;
            warp_gemm_t<0>(wsm, wsm_u, g_xT, M0, moff, g_wt0, F1, F0,
                           b0, g_cur0T, M0, moff, nullptr, bm, bn, lane);
        } else if ((int)tk < nL1 + nL0 + nSP) {
            const int j = tk - nL1 - nL0;
            const int b = j >> 1, n0 = (j & 1) * 512;
            sparse_l2(spS + (size_t)b * F2, g_wt2, b2,
                      g_m2RM + (size_t)b * F3, out_t + (size_t)b * F3, n0, lane);
        } else {
            const int c = tk - nL1 - nL0 - nSP;
            const float4* c4 = reinterpret_cast<const float4*>(g_cur0T);
            float4* m4 = reinterpret_cast<float4*>(g_m0T);
            float4* s4 = reinterpret_cast<float4*>(g_s0T[lif_t & 1]);
            const int toff4 = lif_t * (BATCH / 4);
            #pragma unroll 4
            for (int j = 0; j < 128; j++) {
                int f4 = c * 4096 + j * 32 + lane;
                int n = f4 >> 6, b4 = f4 & 63;
                float4 cur = c4[(size_t)n * (M0 / 4) + toff4 + b4];
                float4 m = (lif_t == 0) ? make_float4(0.f, 0.f, 0.f, 0.f) : m4[f4];
                float4 s;
                lif_update(m.x, cur.x, m.x, s.x);
                lif_update(m.y, cur.y, m.y, s.y);
                lif_update(m.z, cur.z, m.z, s.z);
                lif_update(m.w, cur.w, m.w, s.w);
                m4[f4] = m;
                s4[f4] = s;
            }
        }
    }
}

// ---------------------------------------------------------------------------
extern "C" void kernel_launch(void* const* d_in, const int* in_sizes, int n_in,
                              void* d_out, int out_size)
{
    (void)in_sizes; (void)n_in;
    const float* x  = (const float*)d_in[0];
    const float* w0 = (const float*)d_in[1];
    const float* b0 = (const float*)d_in[2];
    const float* w1 = (const float*)d_in[3];
    const float* b1 = (const float*)d_in[4];
    const float* w2 = (const float*)d_in[5];
    const float* b2 = (const float*)d_in[6];
    float* out = (float*)d_out;

    float *wt0, *wt1, *wt2, *xT;
    cudaGetSymbolAddress((void**)&wt0, g_wt0);
    cudaGetSymbolAddress((void**)&wt1, g_wt1);
    cudaGetSymbolAddress((void**)&wt2, g_wt2);
    cudaGetSymbolAddress((void**)&xT,  g_xT);

    // prep: transposes (weights + x) and zero (membranes, tickets)
    {
        dim3 blk(32, 8);
        transpose_kernel<<<dim3(F0 / 32, F1 / 32), blk>>>(w0, wt0, F1, F0);
        transpose_kernel<<<dim3(F1 / 32, F2 / 32), blk>>>(w1, wt1, F2, F1);
        transpose_kernel<<<dim3(F2 / 32, F3 / 32), blk>>>(w2, wt2, F3, F2);
        transpose_kernel<<<dim3(F0 / 32, M0 / 32), blk>>>(x, xT, M0, F0);
        zero_mems_kernel<<<512, 256>>>();
    }

    const int GRID = 444;   // 3 CTAs per SM
    int li = 0;

    // P0: L0 slices 0,1,2
    step_kernel<<<GRID, 128>>>(li++, 0, 0, 3 * 512, 0, 0, 0, 0, 0,
                               b0, b1, b2, nullptr);
    // P1: L0 slice 3 + lif0(0)
    step_kernel<<<GRID, 128>>>(li++, 0, 0, 512, 3, 0, 0, 32, 0,
                               b0, b1, b2, nullptr);
    // P2: L1(0) + L0 slice 4 + lif0(1)
    step_kernel<<<GRID, 128>>>(li++, 512, 0, 512, 4, 0, 0, 32, 1,
                               b0, b1, b2, nullptr);

    // steps t = 0..23: L2(t) + L1(t+1) + lif0(t+2) + L0 slice(t+5)
    for (int t = 0; t < T_STEPS - 1; ++t) {
        const int nLIF = (t + 2 <= T_STEPS - 1) ? 32 : 0;
        const int nL0  = (t + 5 <= T_STEPS - 1) ? 512 : 0;
        step_kernel<<<GRID, 128>>>(li++,
                                   512, (t + 1) & 1,
                                   nL0, t + 5,
                                   512, t & 1,
                                   nLIF, t + 2,
                                   b0, b1, b2,
                                   out + (size_t)t * BATCH * F3);
    }
    // final: L2(24)
    step_kernel<<<GRID, 128>>>(li++, 0, 0, 0, 0, 512, (T_STEPS - 1) & 1, 0, 0,
                               b0, b1, b2,
                               out + (size_t)(T_STEPS - 1) * BATCH * F3);

    const long long mem_off = (long long)T_STEPS * BATCH * F3;
    if ((long long)out_size >= mem_off + (long long)BATCH * F3) {
        copy_final_mem_kernel<<<(BATCH * F3 + 255) / 256, 256>>>(out + mem_off);
    }
}